// round 7
// baseline (speedup 1.0000x reference)
#include <cuda_runtime.h>
#include <cuda_fp16.h>
#include <cstdint>

#define MAXN   100000
#define MAXNNZ 800000
#define MAXNE  1600000
#define SCAN_B 1024

// ---------------------------------------------------------------------------
// Scratch (static device globals — allocation-free).
// g_xw stored in fp16: halves pass-2 gather traffic (L2-bound).
// ---------------------------------------------------------------------------
__device__ __half g_xw[(size_t)MAXN * 128];

// Per-side CSR scratch (X side feeds pass1, A side feeds pass2 — independent).
__device__ int g_cnt_x[MAXN], g_cur_x[MAXN], g_row_x[MAXN + 1], g_bsum_x[128];
__device__ int g_cnt_a[MAXN], g_cur_a[MAXN], g_row_a[MAXN + 1], g_bsum_a[128];

__device__ float2 g_px[MAXNNZ];   // permuted X nnz: (val, bitcast col)
__device__ float2 g_pa[MAXNE];    // permuted A nnz: (val, bitcast src)

// ---------------------------------------------------------------------------
// Histogram: cnt[rows[i]]++  (grid-stride, 4 per thread)
// ---------------------------------------------------------------------------
__global__ void __launch_bounds__(256) hist_kernel(
    const int* __restrict__ rows, int n, int* __restrict__ cnt)
{
    int i = (blockIdx.x * blockDim.x + threadIdx.x) * 4;
    if (i + 3 < n) {
        int4 r = *reinterpret_cast<const int4*>(rows + i);
        atomicAdd(&cnt[r.x], 1);
        atomicAdd(&cnt[r.y], 1);
        atomicAdd(&cnt[r.z], 1);
        atomicAdd(&cnt[r.w], 1);
    } else {
        for (int k = i; k < n; ++k) atomicAdd(&cnt[rows[k]], 1);
    }
}

// ---------------------------------------------------------------------------
// Scan stage 1: per-block (1024) inclusive scan + block sums.
// ---------------------------------------------------------------------------
__global__ void __launch_bounds__(SCAN_B) scan_block_kernel(
    const int* __restrict__ cnt, int* __restrict__ incl,
    int* __restrict__ bsum, int n)
{
    __shared__ int sh[SCAN_B];
    int gid = blockIdx.x * SCAN_B + threadIdx.x;
    int v = (gid < n) ? cnt[gid] : 0;
    sh[threadIdx.x] = v;
    __syncthreads();
#pragma unroll
    for (int off = 1; off < SCAN_B; off <<= 1) {
        int t = (threadIdx.x >= off) ? sh[threadIdx.x - off] : 0;
        __syncthreads();
        sh[threadIdx.x] += t;
        __syncthreads();
    }
    if (gid < n) incl[gid] = sh[threadIdx.x];
    if (threadIdx.x == SCAN_B - 1) bsum[blockIdx.x] = sh[SCAN_B - 1];
}

// ---------------------------------------------------------------------------
// Scan stage 2: exclusive scan of block sums (single block, nb <= 1024).
// ---------------------------------------------------------------------------
__global__ void __launch_bounds__(SCAN_B) scan_sums_kernel(int* __restrict__ bsum, int nb)
{
    __shared__ int sh[SCAN_B];
    int v = (threadIdx.x < nb) ? bsum[threadIdx.x] : 0;
    sh[threadIdx.x] = v;
    __syncthreads();
#pragma unroll
    for (int off = 1; off < SCAN_B; off <<= 1) {
        int t = (threadIdx.x >= off) ? sh[threadIdx.x - off] : 0;
        __syncthreads();
        sh[threadIdx.x] += t;
        __syncthreads();
    }
    if (threadIdx.x < nb) bsum[threadIdx.x] = sh[threadIdx.x] - v;  // exclusive
}

// ---------------------------------------------------------------------------
// Scan stage 3: row_start = incl + bsum[blk] - cnt; also initializes cur.
// ---------------------------------------------------------------------------
__global__ void __launch_bounds__(256) finalize_kernel(
    const int* __restrict__ incl, const int* __restrict__ bsum,
    const int* __restrict__ cnt, int* __restrict__ row_start,
    int* __restrict__ cur, int n)
{
    int gid = blockIdx.x * blockDim.x + threadIdx.x;
    if (gid >= n) return;
    int e  = incl[gid] + bsum[gid >> 10];
    int st = e - cnt[gid];
    row_start[gid] = st;
    cur[gid]       = st;
    if (gid == n - 1) row_start[n] = e;
}

// ---------------------------------------------------------------------------
// Permutation scatter: bucket (val, col/src) pairs by destination row.
// cur[] pre-initialized to row_start by finalize.
// ---------------------------------------------------------------------------
__global__ void __launch_bounds__(256) scatter_kernel(
    const float* __restrict__ vals, const int* __restrict__ rows,
    const int* __restrict__ cols, int* __restrict__ cur,
    float2* __restrict__ perm, int n)
{
    int i = blockIdx.x * blockDim.x + threadIdx.x;
    if (i >= n) return;
    int r   = rows[i];
    int pos = atomicAdd(&cur[r], 1);
    perm[pos] = make_float2(vals[i], __int_as_float(cols[i]));
}

// ---------------------------------------------------------------------------
// Pass 1 (CSR): xw[r,:] = sum_j val_j * W[col_j,:], stored fp16.
// One warp per row; lane l owns floats [4l,4l+4). Single 8B store per lane.
// ---------------------------------------------------------------------------
__global__ void __launch_bounds__(256) spmm_xw_kernel(
    const int* __restrict__ row_start, const float2* __restrict__ perm,
    const float* __restrict__ W, int N)
{
    int warp = (blockIdx.x * blockDim.x + threadIdx.x) >> 5;
    int lane = threadIdx.x & 31;
    if (warp >= N) return;
    int s = row_start[warp], e = row_start[warp + 1];

    float4 acc = make_float4(0.f, 0.f, 0.f, 0.f);
    int j = s;
    for (; j + 1 < e; j += 2) {
        float2 p0 = perm[j], p1 = perm[j + 1];
        float4 w0 = __ldg((const float4*)W + (size_t)__float_as_int(p0.y) * 32 + lane);
        float4 w1 = __ldg((const float4*)W + (size_t)__float_as_int(p1.y) * 32 + lane);
        acc.x = fmaf(p0.x, w0.x, acc.x); acc.y = fmaf(p0.x, w0.y, acc.y);
        acc.z = fmaf(p0.x, w0.z, acc.z); acc.w = fmaf(p0.x, w0.w, acc.w);
        acc.x = fmaf(p1.x, w1.x, acc.x); acc.y = fmaf(p1.x, w1.y, acc.y);
        acc.z = fmaf(p1.x, w1.z, acc.z); acc.w = fmaf(p1.x, w1.w, acc.w);
    }
    if (j < e) {
        float2 p = perm[j];
        float4 w = __ldg((const float4*)W + (size_t)__float_as_int(p.y) * 32 + lane);
        acc.x = fmaf(p.x, w.x, acc.x); acc.y = fmaf(p.x, w.y, acc.y);
        acc.z = fmaf(p.x, w.z, acc.z); acc.w = fmaf(p.x, w.w, acc.w);
    }
    __half2 h01 = __floats2half2_rn(acc.x, acc.y);
    __half2 h23 = __floats2half2_rn(acc.z, acc.w);
    uint2 packed = make_uint2(*reinterpret_cast<uint32_t*>(&h01),
                              *reinterpret_cast<uint32_t*>(&h23));
    reinterpret_cast<uint2*>(g_xw)[(size_t)warp * 32 + lane] = packed;
}

// ---------------------------------------------------------------------------
// Pass 2 (CSR): out[r,:] = relu( sum_e val_e * xw_h[src_e,:] ).
// One warp per dst row; 256B coalesced fp16 gathers from L2, unroll x4.
// ---------------------------------------------------------------------------
__device__ __forceinline__ void fma_row(float4& acc, float v, uint2 raw)
{
    __half2 h01 = *reinterpret_cast<__half2*>(&raw.x);
    __half2 h23 = *reinterpret_cast<__half2*>(&raw.y);
    float2 f01 = __half22float2(h01);
    float2 f23 = __half22float2(h23);
    acc.x = fmaf(v, f01.x, acc.x); acc.y = fmaf(v, f01.y, acc.y);
    acc.z = fmaf(v, f23.x, acc.z); acc.w = fmaf(v, f23.y, acc.w);
}

__global__ void __launch_bounds__(256) spmm_agg_kernel(
    const int* __restrict__ row_start, const float2* __restrict__ perm,
    float* __restrict__ out, int N)
{
    int warp = (blockIdx.x * blockDim.x + threadIdx.x) >> 5;
    int lane = threadIdx.x & 31;
    if (warp >= N) return;
    int s = row_start[warp], e = row_start[warp + 1];

    const uint2* xw2 = reinterpret_cast<const uint2*>(g_xw);
    float4 acc = make_float4(0.f, 0.f, 0.f, 0.f);
    int j = s;
    for (; j + 3 < e; j += 4) {
        float2 p0 = perm[j],     p1 = perm[j + 1];
        float2 p2 = perm[j + 2], p3 = perm[j + 3];
        uint2 r0 = __ldg(xw2 + (size_t)__float_as_int(p0.y) * 32 + lane);
        uint2 r1 = __ldg(xw2 + (size_t)__float_as_int(p1.y) * 32 + lane);
        uint2 r2 = __ldg(xw2 + (size_t)__float_as_int(p2.y) * 32 + lane);
        uint2 r3 = __ldg(xw2 + (size_t)__float_as_int(p3.y) * 32 + lane);
        fma_row(acc, p0.x, r0);
        fma_row(acc, p1.x, r1);
        fma_row(acc, p2.x, r2);
        fma_row(acc, p3.x, r3);
    }
    for (; j < e; ++j) {
        float2 p = perm[j];
        uint2 r = __ldg(xw2 + (size_t)__float_as_int(p.y) * 32 + lane);
        fma_row(acc, p.x, r);
    }
    acc.x = acc.x > 0.f ? acc.x : 0.f;
    acc.y = acc.y > 0.f ? acc.y : 0.f;
    acc.z = acc.z > 0.f ? acc.z : 0.f;
    acc.w = acc.w > 0.f ? acc.w : 0.f;
    reinterpret_cast<float4*>(out)[(size_t)warp * 32 + lane] = acc;
}

// ---------------------------------------------------------------------------
// Launcher: X-side build + pass1 on the main stream; A-side build forked onto
// a secondary stream (event fork/join — capturable, forms a diamond in the
// graph). Critical path: max(X-build + pass1, A-build) + pass2.
// ---------------------------------------------------------------------------
extern "C" void kernel_launch(void* const* d_in, const int* in_sizes, int n_in,
                              void* d_out, int out_size)
{
    const float* x_vals   = (const float*)d_in[0];
    const int*   x_rows   = (const int*)  d_in[1];
    const int*   x_cols   = (const int*)  d_in[2];
    const float* adj_vals = (const float*)d_in[3];
    const int*   adj_rows = (const int*)  d_in[4];
    const int*   adj_cols = (const int*)  d_in[5];
    const float* W        = (const float*)d_in[6];

    int nnz_x   = in_sizes[0];
    int n_edges = in_sizes[3];
    int N       = out_size / 128;

    int *cnt_x, *cur_x, *row_x, *bsum_x;
    int *cnt_a, *cur_a, *row_a, *bsum_a;
    float2 *px, *pa;
    cudaGetSymbolAddress((void**)&cnt_x,  g_cnt_x);
    cudaGetSymbolAddress((void**)&cur_x,  g_cur_x);
    cudaGetSymbolAddress((void**)&row_x,  g_row_x);
    cudaGetSymbolAddress((void**)&bsum_x, g_bsum_x);
    cudaGetSymbolAddress((void**)&cnt_a,  g_cnt_a);
    cudaGetSymbolAddress((void**)&cur_a,  g_cur_a);
    cudaGetSymbolAddress((void**)&row_a,  g_row_a);
    cudaGetSymbolAddress((void**)&bsum_a, g_bsum_a);
    cudaGetSymbolAddress((void**)&px,     g_px);
    cudaGetSymbolAddress((void**)&pa,     g_pa);

    // One-time infrastructure (streams/events are not device memory).
    static cudaStream_t sA = nullptr;
    static cudaEvent_t  evFork = nullptr, evJoin = nullptr;
    if (sA == nullptr) {
        cudaStreamCreateWithFlags(&sA, cudaStreamNonBlocking);
        cudaEventCreateWithFlags(&evFork, cudaEventDisableTiming);
        cudaEventCreateWithFlags(&evJoin, cudaEventDisableTiming);
    }

    const int T = 256;
    int nb_scan = (N + SCAN_B - 1) / SCAN_B;

    // ---- fork: A-side build joins the capture graph via event dependency ----
    cudaEventRecord(evFork, 0);
    cudaStreamWaitEvent(sA, evFork, 0);

    // ---- X-side chain (main stream) ----
    cudaMemsetAsync(cnt_x, 0, N * sizeof(int));
    hist_kernel<<<(nnz_x / 4 + T - 1) / T + 1, T>>>(x_rows, nnz_x, cnt_x);
    scan_block_kernel<<<nb_scan, SCAN_B>>>(cnt_x, cur_x, bsum_x, N);  // cur=temp incl
    scan_sums_kernel<<<1, SCAN_B>>>(bsum_x, nb_scan);
    finalize_kernel<<<(N + T - 1) / T, T>>>(cur_x, bsum_x, cnt_x, row_x, cur_x, N);
    scatter_kernel<<<(nnz_x + T - 1) / T, T>>>(x_vals, x_rows, x_cols,
                                               cur_x, px, nnz_x);
    spmm_xw_kernel<<<(N * 32 + T - 1) / T, T>>>(row_x, px, W, N);

    // ---- A-side chain (secondary stream, concurrent with the above) ----
    cudaMemsetAsync(cnt_a, 0, N * sizeof(int), sA);
    hist_kernel<<<(n_edges / 4 + T - 1) / T + 1, T, 0, sA>>>(adj_rows, n_edges, cnt_a);
    scan_block_kernel<<<nb_scan, SCAN_B, 0, sA>>>(cnt_a, cur_a, bsum_a, N);
    scan_sums_kernel<<<1, SCAN_B, 0, sA>>>(bsum_a, nb_scan);
    finalize_kernel<<<(N + T - 1) / T, T, 0, sA>>>(cur_a, bsum_a, cnt_a, row_a, cur_a, N);
    scatter_kernel<<<(n_edges + T - 1) / T, T, 0, sA>>>(adj_vals, adj_rows, adj_cols,
                                                        cur_a, pa, n_edges);

    // ---- join: pass2 needs pass1 (main) + A-side scatter (sA) ----
    cudaEventRecord(evJoin, sA);
    cudaStreamWaitEvent(0, evJoin, 0);

    spmm_agg_kernel<<<(N * 32 + T - 1) / T, T>>>(row_a, pa, (float*)d_out, N);
}